// round 1
// baseline (speedup 1.0000x reference)
#include <cuda_runtime.h>
#include <math.h>
#include <stdint.h>

#define N_PROP 1024
#define C_FEAT 32
#define ROI 7
#define SR 6
#define SS 42              // ROI*SR
#define D_FEAT 1568        // C_FEAT*ROI*ROI
#define HID 2048
#define NMS_K 100
#define OUT_TOTAL 2600

#define X_MIN (-40.0f)
#define Z_MAX (70.0f)
#define VOX (0.1f)

// ---------------- scratch (device globals; no allocation allowed) ----------
__device__ float g_imgbox[N_PROP * 4];
__device__ float g_bevbox[N_PROP * 4];
__device__ float g_fused[N_PROP * D_FEAT];
__device__ float g_h1[N_PROP * HID];
__device__ float g_h2[N_PROP * HID];
__device__ float g_heads[N_PROP * 14];
__device__ float g_obj_soft[N_PROP * 2];
__device__ float g_pred[N_PROP * 6];
__device__ float g_predbev[N_PROP * 4];
__device__ float g_scores[N_PROP];
__device__ float g_orient[N_PROP];
__device__ int   g_idx[NMS_K];

// ---------------- projections ----------------------------------------------
__global__ void project_kernel(const float* __restrict__ anchors,
                               const float* __restrict__ calib,
                               const int* __restrict__ image_shape)
{
    int n = blockIdx.x * blockDim.x + threadIdx.x;
    if (n >= N_PROP) return;
    const float* a = anchors + n * 6;
    float x = a[0], y = a[1], z = a[2];
    float dx = a[3], dy = a[4], dz = a[5];

    // BEV box
    g_bevbox[n*4+0] = (x - dx*0.5f - X_MIN) / VOX;
    g_bevbox[n*4+1] = (Z_MAX - (z + dz*0.5f)) / VOX;
    g_bevbox[n*4+2] = (x + dx*0.5f - X_MIN) / VOX;
    g_bevbox[n*4+3] = (Z_MAX - (z - dz*0.5f)) / VOX;

    // image box: project 8 corners
    float P[12];
#pragma unroll
    for (int i = 0; i < 12; i++) P[i] = calib[i];
    float Hf = (float)image_shape[0];
    float Wf = (float)image_shape[1];

    float umin = 1e30f, umax = -1e30f, vmin = 1e30f, vmax = -1e30f;
#pragma unroll
    for (int k = 0; k < 8; k++) {
        float sx = (k & 4) ? 1.f : -1.f;
        float sy = (k & 2) ? 1.f : -1.f;
        float sz = (k & 1) ? 1.f : -1.f;
        float cx = x + sx * dx * 0.5f;
        float cy = y + sy * dy * 0.5f;
        float cz = z + sz * dz * 0.5f;
        float px = P[0]*cx + P[1]*cy + P[2]*cz + P[3];
        float py = P[4]*cx + P[5]*cy + P[6]*cz + P[7];
        float pz = P[8]*cx + P[9]*cy + P[10]*cz + P[11];
        float zz = fmaxf(pz, 0.1f);
        float u = px / zz, v = py / zz;
        umin = fminf(umin, u); umax = fmaxf(umax, u);
        vmin = fminf(vmin, v); vmax = fmaxf(vmax, v);
    }
    g_imgbox[n*4+0] = fminf(fmaxf(umin, 0.f), Wf);
    g_imgbox[n*4+1] = fminf(fmaxf(vmin, 0.f), Hf);
    g_imgbox[n*4+2] = fminf(fmaxf(umax, 0.f), Wf);
    g_imgbox[n*4+3] = fminf(fmaxf(vmax, 0.f), Hf);
}

// ---------------- ROI align + fuse -----------------------------------------
// phase 0: g_fused = mi * roi(img)    (boxes = g_imgbox)
// phase 1: g_fused = (g_fused + mb * roi(bev)) / (mi + mb)
__global__ void roi_kernel(const float* __restrict__ feat,
                           const float* __restrict__ boxes,
                           int H, int W,
                           const float* __restrict__ mi,
                           const float* __restrict__ mb,
                           int phase)
{
    int n = blockIdx.x;
    float bx1 = boxes[n*4+0] - 0.5f;
    float by1 = boxes[n*4+1] - 0.5f;
    float bx2 = boxes[n*4+2] - 0.5f;
    float by2 = boxes[n*4+3] - 0.5f;
    float dxw = bx2 - bx1;
    float dyh = by2 - by1;
    float sc  = (phase == 0) ? mi[0] : mb[0];
    float inv = (phase == 0) ? 1.f : 1.f / (mi[0] + mb[0]);

    for (int o = threadIdx.x; o < D_FEAT; o += blockDim.x) {
        int c = o / 49;
        int r = o % 49;
        int py = r / 7;
        int px = r % 7;
        const float* fc = feat + (size_t)c * H * W;

        int x0i[SR], x1i[SR];
        float wx[SR];
#pragma unroll
        for (int sx = 0; sx < SR; sx++) {
            float g = ((float)(px * SR + sx) + 0.5f) / (float)SS;
            float xs = bx1 + g * dxw;
            float xf = fminf(fmaxf(floorf(xs), 0.f), (float)(W - 1));
            wx[sx] = fminf(fmaxf(xs - xf, 0.f), 1.f);
            int xi = (int)xf;
            x0i[sx] = xi;
            x1i[sx] = min(xi + 1, W - 1);
        }

        float sum = 0.f;
#pragma unroll
        for (int sy = 0; sy < SR; sy++) {
            float g = ((float)(py * SR + sy) + 0.5f) / (float)SS;
            float ys = by1 + g * dyh;
            float yf = fminf(fmaxf(floorf(ys), 0.f), (float)(H - 1));
            float wy = fminf(fmaxf(ys - yf, 0.f), 1.f);
            int yi = (int)yf;
            int yj = min(yi + 1, H - 1);
            const float* row0 = fc + (size_t)yi * W;
            const float* row1 = fc + (size_t)yj * W;
#pragma unroll
            for (int sx = 0; sx < SR; sx++) {
                float f00 = row0[x0i[sx]];
                float f01 = row0[x1i[sx]];
                float f10 = row1[x0i[sx]];
                float f11 = row1[x1i[sx]];
                float w = wx[sx];
                float top = f00 * (1.f - w) + f01 * w;
                float bot = f10 * (1.f - w) + f11 * w;
                sum += top * (1.f - wy) + bot * wy;
            }
        }
        float val = sum * (1.f / 36.f);
        size_t oi = (size_t)n * D_FEAT + o;
        if (phase == 0) g_fused[oi] = sc * val;
        else            g_fused[oi] = (g_fused[oi] + sc * val) * inv;
    }
}

// ---------------- SGEMM: C = relu?(A @ B + bias) ---------------------------
// A: M x K, B: K x N, M,N multiples of 128, K multiple of 16.
template<int RELU>
__global__ __launch_bounds__(256, 2)
void gemm_kernel(const float* __restrict__ A, const float* __restrict__ B,
                 const float* __restrict__ bias, float* __restrict__ C,
                 int M, int N, int K)
{
    const int BM = 128, BN = 128, BK = 16;
    __shared__ float As[BK][BM];
    __shared__ float Bs[BK][BN];

    int tid = threadIdx.x;
    int tx = tid & 15;       // 0..15 -> col group
    int ty = tid >> 4;       // 0..15 -> row group
    int m0 = blockIdx.y * BM;
    int n0 = blockIdx.x * BN;

    float acc[8][8];
#pragma unroll
    for (int i = 0; i < 8; i++)
#pragma unroll
        for (int j = 0; j < 8; j++) acc[i][j] = 0.f;

    for (int k0 = 0; k0 < K; k0 += BK) {
        // load A tile (128x16) -> As[k][m] (transposed)
#pragma unroll
        for (int l = 0; l < 2; l++) {
            int idx = tid + l * 256;        // float4 id, 0..511
            int row = idx >> 2;             // 0..127
            int kc  = (idx & 3) << 2;       // 0,4,8,12
            float4 v = *reinterpret_cast<const float4*>(
                A + (size_t)(m0 + row) * K + k0 + kc);
            As[kc + 0][row] = v.x;
            As[kc + 1][row] = v.y;
            As[kc + 2][row] = v.z;
            As[kc + 3][row] = v.w;
        }
        // load B tile (16x128) -> Bs[k][n]
#pragma unroll
        for (int l = 0; l < 2; l++) {
            int idx = tid + l * 256;        // float4 id
            int kk = idx >> 5;              // 0..15
            int c4 = idx & 31;              // 0..31
            float4 v = *reinterpret_cast<const float4*>(
                B + (size_t)(k0 + kk) * N + n0 + (c4 << 2));
            *reinterpret_cast<float4*>(&Bs[kk][c4 << 2]) = v;
        }
        __syncthreads();

#pragma unroll
        for (int kk = 0; kk < BK; kk++) {
            float a[8], b[8];
            *reinterpret_cast<float4*>(a)     = *reinterpret_cast<float4*>(&As[kk][ty * 8]);
            *reinterpret_cast<float4*>(a + 4) = *reinterpret_cast<float4*>(&As[kk][ty * 8 + 4]);
            *reinterpret_cast<float4*>(b)     = *reinterpret_cast<float4*>(&Bs[kk][tx * 8]);
            *reinterpret_cast<float4*>(b + 4) = *reinterpret_cast<float4*>(&Bs[kk][tx * 8 + 4]);
#pragma unroll
            for (int i = 0; i < 8; i++)
#pragma unroll
                for (int j = 0; j < 8; j++)
                    acc[i][j] = fmaf(a[i], b[j], acc[i][j]);
        }
        __syncthreads();
    }

    // epilogue
#pragma unroll
    for (int i = 0; i < 8; i++) {
        int mrow = m0 + ty * 8 + i;
#pragma unroll
        for (int j4 = 0; j4 < 2; j4++) {
            int ncol = n0 + tx * 8 + j4 * 4;
            float4 bv = *reinterpret_cast<const float4*>(bias + ncol);
            float4 o;
            o.x = acc[i][j4*4+0] + bv.x;
            o.y = acc[i][j4*4+1] + bv.y;
            o.z = acc[i][j4*4+2] + bv.z;
            o.w = acc[i][j4*4+3] + bv.w;
            if (RELU) {
                o.x = fmaxf(o.x, 0.f); o.y = fmaxf(o.y, 0.f);
                o.z = fmaxf(o.z, 0.f); o.w = fmaxf(o.w, 0.f);
            }
            *reinterpret_cast<float4*>(C + (size_t)mrow * N + ncol) = o;
        }
    }
}

// ---------------- heads: obj(2), off(10), ang(2) ----------------------------
__global__ void heads_kernel(const float* __restrict__ Wc, const float* __restrict__ bc,
                             const float* __restrict__ Wo, const float* __restrict__ bo,
                             const float* __restrict__ Wa, const float* __restrict__ ba)
{
    int row = blockIdx.x;
    int t = threadIdx.x;         // 128 threads
    float acc[14];
#pragma unroll
    for (int c = 0; c < 14; c++) acc[c] = 0.f;

    const float* h = g_h2 + (size_t)row * HID;
    for (int k = t; k < HID; k += 128) {
        float hv = h[k];
        acc[0]  = fmaf(hv, Wc[k*2+0], acc[0]);
        acc[1]  = fmaf(hv, Wc[k*2+1], acc[1]);
#pragma unroll
        for (int j = 0; j < 10; j++)
            acc[2+j] = fmaf(hv, Wo[k*10+j], acc[2+j]);
        acc[12] = fmaf(hv, Wa[k*2+0], acc[12]);
        acc[13] = fmaf(hv, Wa[k*2+1], acc[13]);
    }

    __shared__ float red[128];
#pragma unroll
    for (int c = 0; c < 14; c++) {
        red[t] = acc[c];
        __syncthreads();
        for (int s = 64; s > 0; s >>= 1) {
            if (t < s) red[t] += red[t + s];
            __syncthreads();
        }
        if (t == 0) {
            float b = (c < 2) ? bc[c] : (c < 12 ? bo[c-2] : ba[c-12]);
            g_heads[row*14 + c] = red[0] + b;
        }
        __syncthreads();
    }
}

// ---------------- post: softmax, pred anchors, pred_bev, scores, orient ----
__global__ void post_kernel(const float* __restrict__ anchors)
{
    int n = blockIdx.x * blockDim.x + threadIdx.x;
    if (n >= N_PROP) return;
    const float* hd = g_heads + n * 14;
    float o0 = hd[0], o1 = hd[1];
    float m = fmaxf(o0, o1);
    float e0 = expf(o0 - m), e1 = expf(o1 - m);
    float inv = 1.f / (e0 + e1);
    g_obj_soft[n*2+0] = e0 * inv;
    g_obj_soft[n*2+1] = e1 * inv;
    g_scores[n] = o1;                     // obj[:,1:].max(1) with 2 classes
    g_orient[n] = atan2f(hd[13], hd[12]);

    float p[6];
#pragma unroll
    for (int i = 0; i < 6; i++) {
        p[i] = anchors[n*6+i] + hd[2+i];
        g_pred[n*6+i] = p[i];
    }
    float x = p[0], z = p[2], dx = p[3], dz = p[5];
    g_predbev[n*4+0] = (x - dx*0.5f - X_MIN) / VOX;
    g_predbev[n*4+1] = (Z_MAX - (z + dz*0.5f)) / VOX;
    g_predbev[n*4+2] = (x + dx*0.5f - X_MIN) / VOX;
    g_predbev[n*4+3] = (Z_MAX - (z - dz*0.5f)) / VOX;
}

// ---------------- NMS (exact replica of the scan loop) ----------------------
__global__ void nms_kernel()
{
    int t = threadIdx.x;   // 1024 threads, 1 block
    __shared__ float ss[N_PROP];
    __shared__ float sval[32];
    __shared__ int   sidx[32];
    __shared__ float sb[4];
    __shared__ int   scur;

    float ax1 = g_predbev[t*4+0];
    float ay1 = g_predbev[t*4+1];
    float ax2 = g_predbev[t*4+2];
    float ay2 = g_predbev[t*4+3];
    float areaA = (ax2 - ax1) * (ay2 - ay1);
    ss[t] = g_scores[t];
    __syncthreads();

    for (int k = 0; k < NMS_K; k++) {
        float v = ss[t];
        int bi = t;
#pragma unroll
        for (int off = 16; off > 0; off >>= 1) {
            float ov = __shfl_down_sync(0xffffffffu, v, off);
            int   oi = __shfl_down_sync(0xffffffffu, bi, off);
            if (ov > v || (ov == v && oi < bi)) { v = ov; bi = oi; }
        }
        if ((t & 31) == 0) { sval[t >> 5] = v; sidx[t >> 5] = bi; }
        __syncthreads();
        if (t < 32) {
            v = sval[t]; bi = sidx[t];
#pragma unroll
            for (int off = 16; off > 0; off >>= 1) {
                float ov = __shfl_down_sync(0xffffffffu, v, off);
                int   oi = __shfl_down_sync(0xffffffffu, bi, off);
                if (ov > v || (ov == v && oi < bi)) { v = ov; bi = oi; }
            }
            if (t == 0) {
                scur = bi;
                g_idx[k] = bi;
                sb[0] = g_predbev[bi*4+0];
                sb[1] = g_predbev[bi*4+1];
                sb[2] = g_predbev[bi*4+2];
                sb[3] = g_predbev[bi*4+3];
            }
        }
        __syncthreads();
        float bx1 = sb[0], by1 = sb[1], bx2 = sb[2], by2 = sb[3];
        float areaB = (bx2 - bx1) * (by2 - by1);
        float xx1 = fmaxf(ax1, bx1);
        float yy1 = fmaxf(ay1, by1);
        float xx2 = fminf(ax2, bx2);
        float yy2 = fminf(ay2, by2);
        float inter = fmaxf(xx2 - xx1, 0.f) * fmaxf(yy2 - yy1, 0.f);
        float iou = inter / (areaA + areaB - inter + 1e-6f);
        if (iou > 0.01f || t == scur) ss[t] = -INFINITY;
        __syncthreads();
    }
}

// ---------------- gather outputs --------------------------------------------
// layout: obj_soft[idx] (100x2) | pred_anchors[idx] (100x6) | off[idx] (100x10)
//         | pred_box[idx] (100x7) | orient[idx] (100)
__global__ void gather_kernel(float* __restrict__ out)
{
    int i = blockIdx.x * blockDim.x + threadIdx.x;
    if (i >= OUT_TOTAL) return;
    float v;
    if (i < 200) {
        int n = i / 2, c = i % 2;
        v = g_obj_soft[g_idx[n]*2 + c];
    } else if (i < 800) {
        int j = i - 200; int n = j / 6, c = j % 6;
        v = g_pred[g_idx[n]*6 + c];
    } else if (i < 1800) {
        int j = i - 800; int n = j / 10, c = j % 10;
        v = g_heads[g_idx[n]*14 + 2 + c];
    } else if (i < 2500) {
        int j = i - 1800; int n = j / 7, c = j % 7;
        v = (c < 6) ? g_pred[g_idx[n]*6 + c] : 0.f;
    } else {
        int n = i - 2500;
        v = g_orient[g_idx[n]];
    }
    out[i] = v;
}

// ---------------- launch -----------------------------------------------------
extern "C" void kernel_launch(void* const* d_in, const int* in_sizes, int n_in,
                              void* d_out, int out_size)
{
    const float* img_feat = (const float*)d_in[0];   // 1x32x360x1200
    const float* bev_feat = (const float*)d_in[1];   // 1x32x700x800
    const float* anchors  = (const float*)d_in[2];   // 1024x6
    const float* calib    = (const float*)d_in[3];   // 3x4
    // d_in[4] ground_plane: unused (multiplied by 0 in reference)
    const float* img_mask = (const float*)d_in[5];   // scalar
    const float* bev_mask = (const float*)d_in[6];   // scalar
    const float* W1 = (const float*)d_in[7];
    const float* b1 = (const float*)d_in[8];
    const float* W2 = (const float*)d_in[9];
    const float* b2 = (const float*)d_in[10];
    const float* Wc = (const float*)d_in[11];
    const float* bc = (const float*)d_in[12];
    const float* Wo = (const float*)d_in[13];
    const float* bo = (const float*)d_in[14];
    const float* Wa = (const float*)d_in[15];
    const float* ba = (const float*)d_in[16];
    const int* image_shape = (const int*)d_in[17];
    float* out = (float*)d_out;

    void *p_imgbox, *p_bevbox, *p_fused, *p_h1, *p_h2;
    cudaGetSymbolAddress(&p_imgbox, g_imgbox);
    cudaGetSymbolAddress(&p_bevbox, g_bevbox);
    cudaGetSymbolAddress(&p_fused, g_fused);
    cudaGetSymbolAddress(&p_h1, g_h1);
    cudaGetSymbolAddress(&p_h2, g_h2);

    project_kernel<<<8, 128>>>(anchors, calib, image_shape);

    roi_kernel<<<N_PROP, 256>>>(img_feat, (const float*)p_imgbox,
                                360, 1200, img_mask, bev_mask, 0);
    roi_kernel<<<N_PROP, 256>>>(bev_feat, (const float*)p_bevbox,
                                700, 800, img_mask, bev_mask, 1);

    dim3 g1(HID / 128, N_PROP / 128);
    gemm_kernel<1><<<g1, 256>>>((const float*)p_fused, W1, b1, (float*)p_h1,
                                N_PROP, HID, D_FEAT);
    gemm_kernel<1><<<g1, 256>>>((const float*)p_h1, W2, b2, (float*)p_h2,
                                N_PROP, HID, HID);

    heads_kernel<<<N_PROP, 128>>>(Wc, bc, Wo, bo, Wa, ba);
    post_kernel<<<8, 128>>>(anchors);
    nms_kernel<<<1, N_PROP>>>();
    gather_kernel<<<(OUT_TOTAL + 255) / 256, 256>>>(out);
}